// round 5
// baseline (speedup 1.0000x reference)
#include <cuda_runtime.h>

// Problem constants
#define S_DIM  128
#define I_DIM  384
#define IN_D   256
#define PD     32      // PROJ_DIM
#define OD     128     // OUT_DIM
#define IDX    (I_DIM * PD)   // 12288

// Scratch (static device globals -- no runtime allocation)
__device__ float g_L[S_DIM * IDX];       // l[s][i*32+d]
__device__ float g_R[S_DIM * IDX];       // r[s][j*32+e]
__device__ float g_norm[I_DIM * I_DIM];  // mask Gram

// ---- packed f32x2 helpers (FFMA2 path; ptxas never emits these from C++) ----
__device__ __forceinline__ unsigned long long pack_dup(float a) {
    unsigned long long r; unsigned int ai = __float_as_uint(a);
    asm("mov.b64 %0, {%1, %1};" : "=l"(r) : "r"(ai));
    return r;
}
__device__ __forceinline__ void ffma2(unsigned long long& acc,
                                      unsigned long long a, unsigned long long b) {
    asm("fma.rn.f32x2 %0, %1, %2, %0;" : "+l"(acc) : "l"(a), "l"(b));
}
__device__ __forceinline__ float2 unpack2(unsigned long long v) {
    unsigned int lo, hi;
    asm("mov.b64 {%0, %1}, %2;" : "=r"(lo), "=r"(hi) : "l"(v));
    return make_float2(__uint_as_float(lo), __uint_as_float(hi));
}

// ---------------------------------------------------------------------------
// Kernel A: LayerNorm + projection + mask -> g_L, g_R
// One warp per (s,i) row; 8 rows per 256-thread block. W_proj staged in smem.
// ---------------------------------------------------------------------------
__global__ __launch_bounds__(256) void ln_proj_kernel(
    const float* __restrict__ node, const float* __restrict__ mask,
    const float* __restrict__ Wp,   const float* __restrict__ bp)
{
    extern __shared__ float sm[];
    float* Wp_s = sm;            // 256 x 64
    float* xs   = sm + 16384;    // 8 x 256

    int t = threadIdx.x;
    for (int v = t; v < 4096; v += 256)
        ((float4*)Wp_s)[v] = ((const float4*)Wp)[v];

    int w = t >> 5, lane = t & 31;
    int row = blockIdx.x * 8 + w;
    const float* xr = node + (size_t)row * IN_D;

    float xv[8], s1 = 0.f, s2 = 0.f;
#pragma unroll
    for (int u = 0; u < 8; u++) {
        xv[u] = xr[lane + 32 * u];
        s1 += xv[u];
        s2 += xv[u] * xv[u];
    }
#pragma unroll
    for (int off = 16; off > 0; off >>= 1) {
        s1 += __shfl_xor_sync(0xffffffffu, s1, off);
        s2 += __shfl_xor_sync(0xffffffffu, s2, off);
    }
    float mu  = s1 * (1.f / IN_D);
    float var = s2 * (1.f / IN_D) - mu * mu;
    float rs  = rsqrtf(var + 1e-5f);

    float* xrow = xs + w * 256;
#pragma unroll
    for (int u = 0; u < 8; u++) xrow[lane + 32 * u] = (xv[u] - mu) * rs;
    __syncthreads();

    float a0 = 0.f, a1 = 0.f;
#pragma unroll 8
    for (int k = 0; k < 256; k++) {
        float xk = xrow[k];
        a0 = fmaf(xk, Wp_s[k * 64 + lane],      a0);
        a1 = fmaf(xk, Wp_s[k * 64 + lane + 32], a1);
    }
    float m  = mask[row];
    int  si  = row / I_DIM, ii = row % I_DIM;
    g_L[si * IDX + ii * PD + lane] = (a0 + bp[lane])      * m;
    g_R[si * IDX + ii * PD + lane] = (a1 + bp[lane + 32]) * m;
}

// ---------------------------------------------------------------------------
// Kernel B: norm[i][j] = sum_s mask[s,i]*mask[s,j]
// ---------------------------------------------------------------------------
__global__ __launch_bounds__(256) void norm_kernel(const float* __restrict__ mask)
{
    int idx = blockIdx.x * 256 + threadIdx.x;
    int i = idx / I_DIM, j = idx % I_DIM;
    float s = 0.f;
#pragma unroll 4
    for (int ss = 0; ss < S_DIM; ss++)
        s = fmaf(mask[ss * I_DIM + i], mask[ss * I_DIM + j], s);
    g_norm[idx] = s;
}

// ---------------------------------------------------------------------------
// Kernel C: fused pair GEMM, FFMA2 + swizzled A scratch + double-buffered W.
//  Phase 1: A[id=256][je=128] = sum_s L[s][id]*R[s][je]
//           thread tile: rows {lane+32u} (d = lane), cols {cb*64+w*4+cc}
//  A_s layout: A_s[k*32 + ((p + (k>>5)) & 31)], k = d*32+e, p = pi*4+pj.
//  Phase 2: out[p][f] = sum_k A[p][k]*W[k][f]; lanes=pairs, warp w = f-slice.
//           W reads are single-address warp broadcasts.
// ---------------------------------------------------------------------------
__global__ __launch_bounds__(512, 1) void pair_kernel(
    const float* __restrict__ W2,    // [1024][128]
    const float* __restrict__ bias,  // [128]
    float* __restrict__ out)
{
    extern __shared__ float smp[];
    float* A_s = smp;            // 32768 floats = 128 KB (swizzled A)
    float* aux = smp + 32768;    // 16384 floats = 64 KB
    float* Ls  = aux;            // 16 x 256 (phase 1)
    float* Rs  = aux + 4096;     // 16 x 128 (phase 1)

    int t    = threadIdx.x;
    int lane = t & 31, w = t >> 5;        // w: 0..15
    int gi0 = blockIdx.y * 8;
    int gj0 = blockIdx.x * 4;

    unsigned long long acc[8][4];
#pragma unroll
    for (int u = 0; u < 8; u++)
#pragma unroll
        for (int j = 0; j < 4; j++) acc[u][j] = 0ull;

    const float4* Lg4 = (const float4*)g_L;
    const float4* Rg4 = (const float4*)g_R;
    float4* Ls4 = (float4*)Ls;
    float4* Rs4 = (float4*)Rs;
    int lc0 = gi0 * 8;    // float4 col base in L
    int rc0 = gj0 * 8;

    // ---------------- Phase 1 ----------------
    for (int sc = 0; sc < 8; sc++) {
        int sb = sc * 16;
        __syncthreads();
        {
            int v = t;
#pragma unroll
            for (int it = 0; it < 2; it++, v += 512) {
                int ss = v >> 6, c = v & 63;
                Ls4[v] = Lg4[(sb + ss) * 3072 + lc0 + c];
            }
            int ss = t >> 5, c = t & 31;
            Rs4[t] = Rg4[(sb + ss) * 3072 + rc0 + c];
        }
        __syncthreads();
#pragma unroll 4
        for (int ss = 0; ss < 16; ss++) {
            const float* Lrow = Ls + ss * 256;
            unsigned long long ap[8];
#pragma unroll
            for (int u = 0; u < 8; u++) ap[u] = pack_dup(Lrow[lane + 32 * u]);
            // bv: packed pairs straight from smem (16B aligned)
            const ulonglong2* Rrow = (const ulonglong2*)(Rs + ss * 128 + w * 4);
            ulonglong2 b0 = Rrow[0];     // cols w*4 + {0,1},{2,3}      (cb=0)
            ulonglong2 b1 = Rrow[16];    // cols 64 + w*4 + {0,1},{2,3} (cb=1)
            unsigned long long bv[4] = { b0.x, b0.y, b1.x, b1.y };
#pragma unroll
            for (int u = 0; u < 8; u++)
#pragma unroll
                for (int j = 0; j < 4; j++)
                    ffma2(acc[u][j], ap[u], bv[j]);
        }
    }

    // Scatter register tile -> swizzled A_s. Per STS: lanes vary d=lane only,
    // bank = ((p + lane) & 31) -> conflict-free.
#pragma unroll
    for (int u = 0; u < 8; u++)
#pragma unroll
        for (int j = 0; j < 4; j++) {
            float2 v = unpack2(acc[u][j]);
            int col0 = (j >> 1) * 64 + w * 4 + (j & 1) * 2;
            {
                int col = col0, pj = col >> 5, e = col & 31;
                int p = u * 4 + pj;
                A_s[(lane * 32 + e) * 32 + ((p + lane) & 31)] = v.x;
            }
            {
                int col = col0 + 1, pj = col >> 5, e = col & 31;
                int p = u * 4 + pj;
                A_s[(lane * 32 + e) * 32 + ((p + lane) & 31)] = v.y;
            }
        }

    // ---------------- Phase 2 (double-buffered W) ----------------
    float* Wbuf[2] = { aux, aux + 8192 };   // 2 x 32 KB chunks (64 x 128 each)
    const float4* W2g4 = (const float4*)W2;
    unsigned long long o2[4] = {0ull, 0ull, 0ull, 0ull};

    __syncthreads();   // A_s written; Ls/Rs no longer needed
    // Preload chunk 0
#pragma unroll
    for (int it = 0; it < 4; it++) {
        int v = t + it * 512;
        ((float4*)Wbuf[0])[v] = W2g4[v];
    }
    __syncthreads();

    for (int kb = 0; kb < 16; kb++) {
        const float* W_s = Wbuf[kb & 1];
        // Prefetch next chunk into the other buffer (safe: all threads done
        // reading it at the barrier that ended the previous iteration).
        if (kb < 15) {
            float4* Wn = (float4*)Wbuf[(kb + 1) & 1];
#pragma unroll
            for (int it = 0; it < 4; it++) {
                int v = t + it * 512;
                Wn[v] = W2g4[(kb + 1) * 2048 + v];
            }
        }
        const float* pA0 = A_s + (kb * 64) * 32      + ((lane + kb * 2)     & 31);
        const float* pA1 = A_s + (kb * 64 + 32) * 32 + ((lane + kb * 2 + 1) & 31);
        const float* pW  = W_s + w * 8;
#pragma unroll 8
        for (int kl = 0; kl < 32; kl++) {
            unsigned long long a0 = pack_dup(pA0[kl * 32]);
            unsigned long long a1 = pack_dup(pA1[kl * 32]);
            // W reads: one address per warp -> pure broadcast
            ulonglong2 w0a = *(const ulonglong2*)(pW + kl * 128);
            ulonglong2 w0b = *(const ulonglong2*)(pW + kl * 128 + 4);
            ulonglong2 w1a = *(const ulonglong2*)(pW + (32 + kl) * 128);
            ulonglong2 w1b = *(const ulonglong2*)(pW + (32 + kl) * 128 + 4);
            ffma2(o2[0], a0, w0a.x); ffma2(o2[1], a0, w0a.y);
            ffma2(o2[2], a0, w0b.x); ffma2(o2[3], a0, w0b.y);
            ffma2(o2[0], a1, w1a.x); ffma2(o2[1], a1, w1a.y);
            ffma2(o2[2], a1, w1b.x); ffma2(o2[3], a1, w1b.y);
        }
        __syncthreads();
    }

    // Epilogue: lane = pair, warp = f-slice (f = w*8 .. w*8+7)
    int pi = lane >> 2, pj = lane & 3;
    int gi = gi0 + pi, gj = gj0 + pj;
    float inv = 1.f / (g_norm[gi * I_DIM + gj] + 0.001f);
    float2 r0 = unpack2(o2[0]), r1 = unpack2(o2[1]);
    float2 r2 = unpack2(o2[2]), r3 = unpack2(o2[3]);
    float4 b0 = *(const float4*)(bias + w * 8);
    float4 b1 = *(const float4*)(bias + w * 8 + 4);
    float* orow = out + ((size_t)gi * I_DIM + gj) * OD + w * 8;
    *(float4*)(orow)     = make_float4((r0.x + b0.x) * inv, (r0.y + b0.y) * inv,
                                       (r1.x + b0.z) * inv, (r1.y + b0.w) * inv);
    *(float4*)(orow + 4) = make_float4((r2.x + b1.x) * inv, (r2.y + b1.y) * inv,
                                       (r3.x + b1.z) * inv, (r3.y + b1.w) * inv);
}

// ---------------------------------------------------------------------------
extern "C" void kernel_launch(void* const* d_in, const int* in_sizes, int n_in,
                              void* d_out, int out_size)
{
    const float* node = (const float*)d_in[0];
    const float* mask = (const float*)d_in[1];
    const float* Wp   = (const float*)d_in[2];
    const float* bp   = (const float*)d_in[3];
    const float* W2   = (const float*)d_in[4];
    const float* bias = (const float*)d_in[5];
    float* out = (float*)d_out;

    cudaFuncSetAttribute(ln_proj_kernel, cudaFuncAttributeMaxDynamicSharedMemorySize, 73728);
    cudaFuncSetAttribute(pair_kernel,    cudaFuncAttributeMaxDynamicSharedMemorySize, 196608);

    ln_proj_kernel<<<6144, 256, 73728>>>(node, mask, Wp, bp);
    norm_kernel<<<576, 256>>>(mask);
    pair_kernel<<<dim3(96, 48), 512, 196608>>>(W2, bias, out);
}

// round 8
// speedup vs baseline: 3.2360x; 3.2360x over previous
#include <cuda_runtime.h>
#include <cuda_bf16.h>
#include <cstdint>

// Problem constants
#define S_DIM 128
#define I_DIM 384
#define IN_D  256
#define PD    32
#define OD    128

// Scratch (static device globals)
__device__ __nv_bfloat16 g_Lsp[12288 * 256];  // [id][ Lh(128) | Ll(128) ]
__device__ __nv_bfloat16 g_Rsp[12288 * 256];  // [je][ Rh | Rl ]
__device__ __nv_bfloat16 g_Wt [128 * 2048];   // [f ][ Wh(1024) | Wl(1024) ]
__device__ float         g_norm[I_DIM * I_DIM];

// ---------------------------------------------------------------------------
// helpers
// ---------------------------------------------------------------------------
__device__ __forceinline__ uint32_t smem_u32(const void* p) {
    uint32_t a;
    asm("{ .reg .u64 t; cvta.to.shared.u64 t, %1; cvt.u32.u64 %0, t; }"
        : "=r"(a) : "l"(p));
    return a;
}
__device__ __forceinline__ void ldsm_x4(uint32_t* r, uint32_t addr) {
    asm volatile("ldmatrix.sync.aligned.m8n8.x4.shared.b16 {%0,%1,%2,%3}, [%4];"
                 : "=r"(r[0]), "=r"(r[1]), "=r"(r[2]), "=r"(r[3]) : "r"(addr));
}
__device__ __forceinline__ void ldsm_x2(uint32_t* r, uint32_t addr) {
    asm volatile("ldmatrix.sync.aligned.m8n8.x2.shared.b16 {%0,%1}, [%2];"
                 : "=r"(r[0]), "=r"(r[1]) : "r"(addr));
}
__device__ __forceinline__ void mma_bf16(float* d, const uint32_t* a, const uint32_t* b) {
    asm volatile(
        "mma.sync.aligned.m16n8k16.row.col.f32.bf16.bf16.f32 "
        "{%0,%1,%2,%3}, {%4,%5,%6,%7}, {%8,%9}, {%0,%1,%2,%3};"
        : "+f"(d[0]), "+f"(d[1]), "+f"(d[2]), "+f"(d[3])
        : "r"(a[0]), "r"(a[1]), "r"(a[2]), "r"(a[3]), "r"(b[0]), "r"(b[1]));
}
__device__ __forceinline__ void bsplit(float v, __nv_bfloat16& h, __nv_bfloat16& l) {
    h = __float2bfloat16(v);
    l = __float2bfloat16(v - __bfloat162float(h));
}

// ---------------------------------------------------------------------------
// Kernel A: LayerNorm + projection + mask -> split-bf16 scratch (K-major rows)
// ---------------------------------------------------------------------------
__global__ __launch_bounds__(256) void ln_proj_kernel(
    const float* __restrict__ node, const float* __restrict__ mask,
    const float* __restrict__ Wp,   const float* __restrict__ bp)
{
    extern __shared__ float sm[];
    float* Wp_s = sm;            // 256 x 64
    float* xs   = sm + 16384;    // 8 x 256

    int t = threadIdx.x;
    for (int v = t; v < 4096; v += 256)
        ((float4*)Wp_s)[v] = ((const float4*)Wp)[v];

    int w = t >> 5, lane = t & 31;
    int row = blockIdx.x * 8 + w;
    const float* xr = node + (size_t)row * IN_D;

    float xv[8], s1 = 0.f, s2 = 0.f;
#pragma unroll
    for (int u = 0; u < 8; u++) {
        xv[u] = xr[lane + 32 * u];
        s1 += xv[u];
        s2 += xv[u] * xv[u];
    }
#pragma unroll
    for (int off = 16; off > 0; off >>= 1) {
        s1 += __shfl_xor_sync(0xffffffffu, s1, off);
        s2 += __shfl_xor_sync(0xffffffffu, s2, off);
    }
    float mu  = s1 * (1.f / IN_D);
    float var = s2 * (1.f / IN_D) - mu * mu;
    float rs  = rsqrtf(var + 1e-5f);

    float* xrow = xs + w * 256;
#pragma unroll
    for (int u = 0; u < 8; u++) xrow[lane + 32 * u] = (xv[u] - mu) * rs;
    __syncthreads();

    float a0 = 0.f, a1 = 0.f;
#pragma unroll 8
    for (int k = 0; k < 256; k++) {
        float xk = xrow[k];
        a0 = fmaf(xk, Wp_s[k * 64 + lane],      a0);
        a1 = fmaf(xk, Wp_s[k * 64 + lane + 32], a1);
    }
    float m  = mask[row];
    int  si  = row / I_DIM, ii = row % I_DIM;
    float lv = (a0 + bp[lane])      * m;
    float rv = (a1 + bp[lane + 32]) * m;

    __nv_bfloat16 lh, ll, rh, rl;
    bsplit(lv, lh, ll);
    bsplit(rv, rh, rl);

    size_t rb = (size_t)(ii * 32 + lane) * 256;
    g_Lsp[rb + si]       = lh;
    g_Lsp[rb + 128 + si] = ll;
    g_Rsp[rb + si]       = rh;
    g_Rsp[rb + 128 + si] = rl;
}

// ---------------------------------------------------------------------------
// Kernel B: norm Gram
// ---------------------------------------------------------------------------
__global__ __launch_bounds__(256) void norm_kernel(const float* __restrict__ mask)
{
    int idx = blockIdx.x * 256 + threadIdx.x;
    int i = idx / I_DIM, j = idx % I_DIM;
    float s = 0.f;
#pragma unroll 4
    for (int ss = 0; ss < S_DIM; ss++)
        s = fmaf(mask[ss * I_DIM + i], mask[ss * I_DIM + j], s);
    g_norm[idx] = s;
}

// ---------------------------------------------------------------------------
// Kernel B2: transpose + split out_weights -> g_Wt [f][ Wh | Wl ]
// ---------------------------------------------------------------------------
__global__ __launch_bounds__(256) void wprep_kernel(const float* __restrict__ W2)
{
    int idx = blockIdx.x * 256 + threadIdx.x;   // < 131072
    int f = idx >> 10, k = idx & 1023;
    float v = W2[k * 128 + f];
    __nv_bfloat16 h, lo;
    bsplit(v, h, lo);
    g_Wt[f * 2048 + k]        = h;
    g_Wt[f * 2048 + 1024 + k] = lo;
}

// ---------------------------------------------------------------------------
// Kernel C: fused pair GEMM via HMMA (mma.sync m16n8k16 bf16), 3-term split.
//  Phase 1: A1[id=256][je=128] = Lh·Rh + Ll·Rh + Lh·Rl   (K=128 per term)
//  Phase 1.5: split A1 -> A2h/A2l smem [p=32][k=1024] (stride 2064B)
//  Phase 2: out[p=32][f=128] = A2h·Wh + A2l·Wh + A2h·Wl  (K=1024 per term)
// ---------------------------------------------------------------------------
// phase-1 smem (bytes), stride 272 = 256 + 16 pad (conflict-free ldmatrix)
#define OFF_LH 0u
#define OFF_LL 69632u
#define OFF_RH 139264u
#define OFF_RL 174080u
// phase-2 aliases (reuse), A2 stride 2064, W chunk stride 144
#define OFF_A2H 0u
#define OFF_A2L 66048u
#define OFF_WH  132096u
#define OFF_WL  150528u
#define SMEM_SZ 208896

__global__ __launch_bounds__(512, 1) void pair_kernel(
    const float* __restrict__ bias, float* __restrict__ out)
{
    extern __shared__ char smem[];
    uint32_t sb = smem_u32(smem);
    int t = threadIdx.x, lane = t & 31, w = t >> 5;
    int gi0 = blockIdx.y * 8;
    int gj0 = blockIdx.x * 4;

    // ---- load L (256x512B) and R (128x512B) tiles into padded smem ----
    {
        const char* Lg = (const char*)g_Lsp + (size_t)(gi0 * 32) * 512;
#pragma unroll
        for (int it = 0; it < 16; it++) {
            int v = it * 512 + t, r = v >> 5, s = v & 31;
            uint4 x = *(const uint4*)(Lg + (size_t)r * 512 + s * 16);
            *(uint4*)(smem + (s < 16 ? OFF_LH : OFF_LL) + r * 272 + (s & 15) * 16) = x;
        }
        const char* Rg = (const char*)g_Rsp + (size_t)(gj0 * 32) * 512;
#pragma unroll
        for (int it = 0; it < 8; it++) {
            int v = it * 512 + t, r = v >> 5, s = v & 31;
            uint4 x = *(const uint4*)(Rg + (size_t)r * 512 + s * 16);
            *(uint4*)(smem + (s < 16 ? OFF_RH : OFF_RL) + r * 272 + (s & 15) * 16) = x;
        }
    }
    __syncthreads();

    // ---- Phase 1: GEMM1, warp tile M=64 (wm) x N=32 (wn) ----
    int wm = w >> 2, wn = w & 3;
    float D[4][4][4];
#pragma unroll
    for (int a = 0; a < 4; a++)
#pragma unroll
        for (int b = 0; b < 4; b++)
#pragma unroll
            for (int c = 0; c < 4; c++) D[a][b][c] = 0.f;

    uint32_t aRowH = sb + OFF_LH + (wm * 64 + (lane & 15)) * 272 + ((lane >> 4) & 1) * 16;
    uint32_t aRowL = sb + OFF_LL + (wm * 64 + (lane & 15)) * 272 + ((lane >> 4) & 1) * 16;
    uint32_t bRowH = sb + OFF_RH + (wn * 32 + (lane & 7)) * 272 + ((lane >> 3) & 1) * 16;
    uint32_t bRowL = sb + OFF_RL + (wn * 32 + (lane & 7)) * 272 + ((lane >> 3) & 1) * 16;

#pragma unroll
    for (int kk = 0; kk < 8; kk++) {
        uint32_t ko = kk * 32;
        uint32_t ah[4][4], al[4][4];
#pragma unroll
        for (int mt = 0; mt < 4; mt++) {
            ldsm_x4(ah[mt], aRowH + mt * 16 * 272 + ko);
            ldsm_x4(al[mt], aRowL + mt * 16 * 272 + ko);
        }
#pragma unroll
        for (int nt = 0; nt < 4; nt++) {
            uint32_t bh[2], bl[2];
            ldsm_x2(bh, bRowH + nt * 8 * 272 + ko);
            ldsm_x2(bl, bRowL + nt * 8 * 272 + ko);
#pragma unroll
            for (int mt = 0; mt < 4; mt++) {
                mma_bf16(D[mt][nt], ah[mt], bh);
                mma_bf16(D[mt][nt], al[mt], bh);
                mma_bf16(D[mt][nt], ah[mt], bl);
            }
        }
    }
    __syncthreads();   // all warps done reading L/R smem before overwrite

    // ---- Phase 1.5: split accumulators -> A2h / A2l ----
#pragma unroll
    for (int mt = 0; mt < 4; mt++)
#pragma unroll
        for (int nt = 0; nt < 4; nt++)
#pragma unroll
            for (int rr = 0; rr < 2; rr++) {
                int idl = wm * 64 + mt * 16 + (lane >> 2) + rr * 8;
                int p = (idl >> 5) * 4 + wn;
                int d = idl & 31;
                int e = nt * 8 + (lane & 3) * 2;
                uint32_t ofs = (uint32_t)p * 2064 + (uint32_t)(d * 32 + e) * 2;
                __nv_bfloat16 h0, l0, h1, l1;
                bsplit(D[mt][nt][rr * 2 + 0], h0, l0);
                bsplit(D[mt][nt][rr * 2 + 1], h1, l1);
                __nv_bfloat162 ph; ph.x = h0; ph.y = h1;
                __nv_bfloat162 pl; pl.x = l0; pl.y = l1;
                *(__nv_bfloat162*)(smem + OFF_A2H + ofs) = ph;
                *(__nv_bfloat162*)(smem + OFF_A2L + ofs) = pl;
            }
    __syncthreads();

    // ---- Phase 2: GEMM2, warp n8 tile f = w*8..w*8+7, M tiles p0-15/p16-31 ----
    float D2[2][4];
#pragma unroll
    for (int a = 0; a < 2; a++)
#pragma unroll
        for (int c = 0; c < 4; c++) D2[a][c] = 0.f;

    uint32_t a2RowH = sb + OFF_A2H + (lane & 15) * 2064 + ((lane >> 4) & 1) * 16;
    uint32_t a2RowL = sb + OFF_A2L + (lane & 15) * 2064 + ((lane >> 4) & 1) * 16;
    uint32_t bRow2H = sb + OFF_WH + (w * 8 + (lane & 7)) * 144 + ((lane >> 3) & 1) * 16;
    uint32_t bRow2L = sb + OFF_WL + (w * 8 + (lane & 7)) * 144 + ((lane >> 3) & 1) * 16;

    const char* Wg = (const char*)g_Wt;
    uint4 rw[4];
#pragma unroll
    for (int it = 0; it < 4; it++) {
        int v = it * 512 + t, half = v >> 10, v2 = v & 1023, f = v2 >> 3, s = v2 & 7;
        rw[it] = *(const uint4*)(Wg + (size_t)f * 4096 + half * 2048 + s * 16);
    }

    for (int kc = 0; kc < 16; kc++) {
        __syncthreads();   // previous chunk fully consumed
#pragma unroll
        for (int it = 0; it < 4; it++) {
            int v = it * 512 + t, half = v >> 10, v2 = v & 1023, f = v2 >> 3, s = v2 & 7;
            *(uint4*)(smem + (half ? OFF_WL : OFF_WH) + f * 144 + s * 16) = rw[it];
        }
        if (kc < 15) {
#pragma unroll
            for (int it = 0; it < 4; it++) {
                int v = it * 512 + t, half = v >> 10, v2 = v & 1023, f = v2 >> 3, s = v2 & 7;
                rw[it] = *(const uint4*)(Wg + (size_t)f * 4096 + half * 2048
                                         + (kc + 1) * 128 + s * 16);
            }
        }
        __syncthreads();
#pragma unroll
        for (int kk2 = 0; kk2 < 4; kk2++) {
            uint32_t ko = (uint32_t)kc * 128 + kk2 * 32;
            uint32_t a2h[2][4], a2l[2][4];
#pragma unroll
            for (int pm = 0; pm < 2; pm++) {
                ldsm_x4(a2h[pm], a2RowH + pm * 16 * 2064 + ko);
                ldsm_x4(a2l[pm], a2RowL + pm * 16 * 2064 + ko);
            }
            uint32_t bh[2], bl[2];
            ldsm_x2(bh, bRow2H + kk2 * 32);
            ldsm_x2(bl, bRow2L + kk2 * 32);
#pragma unroll
            for (int pm = 0; pm < 2; pm++) {
                mma_bf16(D2[pm], a2h[pm], bh);
                mma_bf16(D2[pm], a2l[pm], bh);
                mma_bf16(D2[pm], a2h[pm], bl);
            }
        }
    }

    // ---- epilogue: bias + divide by (norm + 1e-3) ----
    int f = w * 8 + (lane & 3) * 2;
    float b0 = bias[f], b1 = bias[f + 1];
#pragma unroll
    for (int pm = 0; pm < 2; pm++)
#pragma unroll
        for (int rr = 0; rr < 2; rr++) {
            int p = pm * 16 + (lane >> 2) + rr * 8;
            int gi = gi0 + (p >> 2), gj = gj0 + (p & 3);
            float inv = 1.f / (g_norm[gi * I_DIM + gj] + 0.001f);
            float2 o;
            o.x = (D2[pm][rr * 2 + 0] + b0) * inv;
            o.y = (D2[pm][rr * 2 + 1] + b1) * inv;
            *(float2*)(out + ((size_t)(gi * I_DIM + gj)) * OD + f) = o;
        }
}

// ---------------------------------------------------------------------------
extern "C" void kernel_launch(void* const* d_in, const int* in_sizes, int n_in,
                              void* d_out, int out_size)
{
    const float* node = (const float*)d_in[0];
    const float* mask = (const float*)d_in[1];
    const float* Wp   = (const float*)d_in[2];
    const float* bp   = (const float*)d_in[3];
    const float* W2   = (const float*)d_in[4];
    const float* bias = (const float*)d_in[5];
    float* out = (float*)d_out;

    cudaFuncSetAttribute(ln_proj_kernel, cudaFuncAttributeMaxDynamicSharedMemorySize, 73728);
    cudaFuncSetAttribute(pair_kernel,    cudaFuncAttributeMaxDynamicSharedMemorySize, SMEM_SZ);

    ln_proj_kernel<<<6144, 256, 73728>>>(node, mask, Wp, bp);
    norm_kernel<<<576, 256>>>(mask);
    wprep_kernel<<<512, 256>>>(W2);
    pair_kernel<<<dim3(96, 48), 512, SMEM_SZ>>>(bias, out);
}

// round 10
// speedup vs baseline: 3.6171x; 1.1177x over previous
#include <cuda_runtime.h>
#include <cuda_bf16.h>
#include <cstdint>

// Problem constants
#define S_DIM 128
#define I_DIM 384
#define IN_D  256
#define PD    32
#define OD    128

// Scratch (static device globals)
__device__ __nv_bfloat16 g_Lsp[12288 * 256];  // [id][ Lh(128) | Ll(128) ]
__device__ __nv_bfloat16 g_Rsp[12288 * 256];  // [je][ Rh | Rl ]
__device__ __nv_bfloat16 g_Wt [128 * 2048];   // [f ][ Wh(1024) | Wl(1024) ]
__device__ float         g_norm[I_DIM * I_DIM];

// ---------------------------------------------------------------------------
// helpers
// ---------------------------------------------------------------------------
__device__ __forceinline__ uint32_t smem_u32(const void* p) {
    uint32_t a;
    asm("{ .reg .u64 t; cvta.to.shared.u64 t, %1; cvt.u32.u64 %0, t; }"
        : "=r"(a) : "l"(p));
    return a;
}
__device__ __forceinline__ void ldsm_x4(uint32_t* r, uint32_t addr) {
    asm volatile("ldmatrix.sync.aligned.m8n8.x4.shared.b16 {%0,%1,%2,%3}, [%4];"
                 : "=r"(r[0]), "=r"(r[1]), "=r"(r[2]), "=r"(r[3]) : "r"(addr));
}
__device__ __forceinline__ void mma2(float* d, const uint32_t* a,
                                     uint32_t b0, uint32_t b1) {
    asm volatile(
        "mma.sync.aligned.m16n8k16.row.col.f32.bf16.bf16.f32 "
        "{%0,%1,%2,%3}, {%4,%5,%6,%7}, {%8,%9}, {%0,%1,%2,%3};"
        : "+f"(d[0]), "+f"(d[1]), "+f"(d[2]), "+f"(d[3])
        : "r"(a[0]), "r"(a[1]), "r"(a[2]), "r"(a[3]), "r"(b0), "r"(b1));
}
__device__ __forceinline__ void bsplit(float v, __nv_bfloat16& h, __nv_bfloat16& l) {
    h = __float2bfloat16(v);
    l = __float2bfloat16(v - __bfloat162float(h));
}
__device__ __forceinline__ void cpa16(uint32_t s, const void* g) {
    asm volatile("cp.async.cg.shared.global [%0], [%1], 16;" :: "r"(s), "l"(g));
}
#define CPA_COMMIT() asm volatile("cp.async.commit_group;" ::: "memory")
#define CPA_WAIT1()  asm volatile("cp.async.wait_group 1;" ::: "memory")
#define CPA_WAIT0()  asm volatile("cp.async.wait_group 0;" ::: "memory")

// ---------------------------------------------------------------------------
// Kernel A: LayerNorm + projection + mask -> split-bf16 scratch
// W_proj transposed in smem (stride 260 floats: conflict-free float4 rows)
// ---------------------------------------------------------------------------
__global__ __launch_bounds__(256) void ln_proj_kernel(
    const float* __restrict__ node, const float* __restrict__ mask,
    const float* __restrict__ Wp,   const float* __restrict__ bp)
{
    extern __shared__ float sm[];
    float* Wt_s = sm;            // 64 rows x 260 floats (66560 B)
    float* xs   = sm + 16640;    // 8 x 256 floats

    int t = threadIdx.x;
    for (int v = t; v < 16384; v += 256) {
        int k = v >> 6, c = v & 63;
        Wt_s[c * 260 + k] = Wp[v];
    }

    int w = t >> 5, lane = t & 31;
    int row = blockIdx.x * 8 + w;
    const float* xr = node + (size_t)row * IN_D;

    float xv[8], s1 = 0.f, s2 = 0.f;
#pragma unroll
    for (int u = 0; u < 8; u++) {
        xv[u] = xr[lane + 32 * u];
        s1 += xv[u];
        s2 += xv[u] * xv[u];
    }
#pragma unroll
    for (int off = 16; off > 0; off >>= 1) {
        s1 += __shfl_xor_sync(0xffffffffu, s1, off);
        s2 += __shfl_xor_sync(0xffffffffu, s2, off);
    }
    float mu  = s1 * (1.f / IN_D);
    float var = s2 * (1.f / IN_D) - mu * mu;
    float rs  = rsqrtf(var + 1e-5f);

    float* xrow = xs + w * 256;
#pragma unroll
    for (int u = 0; u < 8; u++) xrow[lane + 32 * u] = (xv[u] - mu) * rs;
    __syncthreads();

    const float4* wr0 = (const float4*)(Wt_s + lane * 260);
    const float4* wr1 = (const float4*)(Wt_s + (lane + 32) * 260);
    const float4* xr4 = (const float4*)xrow;
    float a0 = 0.f, a1 = 0.f;
#pragma unroll 8
    for (int k4 = 0; k4 < 64; k4++) {
        float4 xk = xr4[k4];
        float4 w0 = wr0[k4];
        float4 w1 = wr1[k4];
        a0 = fmaf(xk.x, w0.x, a0); a0 = fmaf(xk.y, w0.y, a0);
        a0 = fmaf(xk.z, w0.z, a0); a0 = fmaf(xk.w, w0.w, a0);
        a1 = fmaf(xk.x, w1.x, a1); a1 = fmaf(xk.y, w1.y, a1);
        a1 = fmaf(xk.z, w1.z, a1); a1 = fmaf(xk.w, w1.w, a1);
    }
    float m  = mask[row];
    int  si  = row / I_DIM, ii = row % I_DIM;
    float lv = (a0 + bp[lane])      * m;
    float rv = (a1 + bp[lane + 32]) * m;

    __nv_bfloat16 lh, ll, rh, rl;
    bsplit(lv, lh, ll);
    bsplit(rv, rh, rl);

    size_t rb = (size_t)(ii * 32 + lane) * 256;
    g_Lsp[rb + si]       = lh;
    g_Lsp[rb + 128 + si] = ll;
    g_Rsp[rb + si]       = rh;
    g_Rsp[rb + 128 + si] = rl;
}

// ---------------------------------------------------------------------------
// Kernel B: norm Gram
// ---------------------------------------------------------------------------
__global__ __launch_bounds__(256) void norm_kernel(const float* __restrict__ mask)
{
    int idx = blockIdx.x * 256 + threadIdx.x;
    int i = idx / I_DIM, j = idx % I_DIM;
    float s = 0.f;
#pragma unroll 4
    for (int ss = 0; ss < S_DIM; ss++)
        s = fmaf(mask[ss * I_DIM + i], mask[ss * I_DIM + j], s);
    g_norm[idx] = s;
}

// ---------------------------------------------------------------------------
// Kernel B2: transpose + split out_weights -> g_Wt [f][ Wh | Wl ]
// ---------------------------------------------------------------------------
__global__ __launch_bounds__(256) void wprep_kernel(const float* __restrict__ W2)
{
    int idx = blockIdx.x * 256 + threadIdx.x;   // < 131072
    int f = idx >> 10, k = idx & 1023;
    float v = W2[k * 128 + f];
    __nv_bfloat16 h, lo;
    bsplit(v, h, lo);
    g_Wt[f * 2048 + k]        = h;
    g_Wt[f * 2048 + 1024 + k] = lo;
}

// ---------------------------------------------------------------------------
// Kernel C: fused pair GEMM via HMMA, 3-term bf16 split.
//  Phase 1: A1[id=256][je=128], warp tile M=64 x N=32, K=128x3 terms
//  Phase 1.5: split A1 -> A2h/A2l smem [p=32][k=1024] (stride 2064B)
//  Phase 2: out[p=32][f=128]; warp = (f-group of 32) x (K-quarter of 256),
//           warp tile M=32 x N=32; 4-way K-reduction via smem at the end.
//           W streamed in k64 chunks, cp.async double-buffered.
// ---------------------------------------------------------------------------
// phase-1 smem (bytes), stride 272 (=16*17, conflict-free ldmatrix)
#define OFF_LH 0u
#define OFF_LL 69632u
#define OFF_RH 139264u
#define OFF_RL 174080u
// phase-2 (aliased): A2 stride 2064 (=16*129)
#define OFF_A2H 0u
#define OFF_A2L 66048u
#define WBUF    132096u    // 2 bufs x (WH 18432 + WL 18432), stride 144 (=16*9)
#define SMEM_SZ 208896

__global__ __launch_bounds__(512, 1) void pair_kernel(
    const float* __restrict__ bias, float* __restrict__ out)
{
    extern __shared__ char smem[];
    uint32_t sb = smem_u32(smem);
    int t = threadIdx.x, lane = t & 31, w = t >> 5;
    int gi0 = blockIdx.y * 8;
    int gj0 = blockIdx.x * 4;

    // ---- load L (256 rows) and R (128 rows) split tiles into padded smem ----
    {
        const char* Lg = (const char*)g_Lsp + (size_t)(gi0 * 32) * 512;
#pragma unroll
        for (int it = 0; it < 16; it++) {
            int v = it * 512 + t, r = v >> 5, s = v & 31;
            uint4 x = *(const uint4*)(Lg + (size_t)r * 512 + s * 16);
            *(uint4*)(smem + (s < 16 ? OFF_LH : OFF_LL) + r * 272 + (s & 15) * 16) = x;
        }
        const char* Rg = (const char*)g_Rsp + (size_t)(gj0 * 32) * 512;
#pragma unroll
        for (int it = 0; it < 8; it++) {
            int v = it * 512 + t, r = v >> 5, s = v & 31;
            uint4 x = *(const uint4*)(Rg + (size_t)r * 512 + s * 16);
            *(uint4*)(smem + (s < 16 ? OFF_RH : OFF_RL) + r * 272 + (s & 15) * 16) = x;
        }
    }
    __syncthreads();

    // ---- Phase 1: warp tile M=64 (wm) x N=32 (wn) ----
    int wm = w >> 2, wn = w & 3;
    float D[4][4][4];
#pragma unroll
    for (int a = 0; a < 4; a++)
#pragma unroll
        for (int b = 0; b < 4; b++)
#pragma unroll
            for (int c = 0; c < 4; c++) D[a][b][c] = 0.f;

    uint32_t aRowH = sb + OFF_LH + (wm * 64 + (lane & 15)) * 272 + ((lane >> 4) & 1) * 16;
    uint32_t aRowL = sb + OFF_LL + (wm * 64 + (lane & 15)) * 272 + ((lane >> 4) & 1) * 16;
    uint32_t bRowH = sb + OFF_RH + (wn * 32 + (lane & 15)) * 272 + ((lane >> 4) & 1) * 16;
    uint32_t bRowL = sb + OFF_RL + (wn * 32 + (lane & 15)) * 272 + ((lane >> 4) & 1) * 16;

#pragma unroll
    for (int kk = 0; kk < 8; kk++) {
        uint32_t ko = kk * 32;
        uint32_t ah[4][4], al[4][4];
#pragma unroll
        for (int mt = 0; mt < 4; mt++) {
            ldsm_x4(ah[mt], aRowH + mt * 16 * 272 + ko);
            ldsm_x4(al[mt], aRowL + mt * 16 * 272 + ko);
        }
#pragma unroll
        for (int g = 0; g < 2; g++) {
            uint32_t bhq[4], blq[4];
            ldsm_x4(bhq, bRowH + g * 16 * 272 + ko);
            ldsm_x4(blq, bRowL + g * 16 * 272 + ko);
#pragma unroll
            for (int s2 = 0; s2 < 2; s2++) {
                int nt = g * 2 + s2;
#pragma unroll
                for (int mt = 0; mt < 4; mt++) {
                    mma2(D[mt][nt], ah[mt], bhq[s2], bhq[s2 + 2]);
                    mma2(D[mt][nt], al[mt], bhq[s2], bhq[s2 + 2]);
                    mma2(D[mt][nt], ah[mt], blq[s2], blq[s2 + 2]);
                }
            }
        }
    }
    __syncthreads();   // all warps done reading L/R smem before overwrite

    // ---- Phase 1.5: split accumulators -> A2h / A2l ----
#pragma unroll
    for (int mt = 0; mt < 4; mt++)
#pragma unroll
        for (int nt = 0; nt < 4; nt++)
#pragma unroll
            for (int rr = 0; rr < 2; rr++) {
                int idl = wm * 64 + mt * 16 + (lane >> 2) + rr * 8;
                int p = (idl >> 5) * 4 + wn;
                int d = idl & 31;
                int e = nt * 8 + (lane & 3) * 2;
                uint32_t ofs = (uint32_t)p * 2064 + (uint32_t)(d * 32 + e) * 2;
                __nv_bfloat16 h0, l0, h1, l1;
                bsplit(D[mt][nt][rr * 2 + 0], h0, l0);
                bsplit(D[mt][nt][rr * 2 + 1], h1, l1);
                __nv_bfloat162 ph; ph.x = h0; ph.y = h1;
                __nv_bfloat162 pl; pl.x = l0; pl.y = l1;
                *(__nv_bfloat162*)(smem + OFF_A2H + ofs) = ph;
                *(__nv_bfloat162*)(smem + OFF_A2L + ofs) = pl;
            }
    __syncthreads();

    // ---- Phase 2: warp = fg (f-group of 32) x ks (K-quarter) ----
    int fg = w & 3, ks = w >> 2;
    float D2[2][4][4];
#pragma unroll
    for (int a = 0; a < 2; a++)
#pragma unroll
        for (int b = 0; b < 4; b++)
#pragma unroll
            for (int c = 0; c < 4; c++) D2[a][b][c] = 0.f;

    uint32_t a2RowH = sb + OFF_A2H + (lane & 15) * 2064 + ((lane >> 4) & 1) * 16;
    uint32_t a2RowL = sb + OFF_A2L + (lane & 15) * 2064 + ((lane >> 4) & 1) * 16;
    const char* Wg = (const char*)g_Wt;

    // chunk copy: k64 (128B/row per half), 2048 cp.async of 16B -> 4/thread
    auto copyW = [&](int kc, int bsel) {
        uint32_t wb = sb + WBUF + (uint32_t)bsel * 36864;
#pragma unroll
        for (int it = 0; it < 4; it++) {
            int v = it * 512 + t;
            int half = v >> 10, v2 = v & 1023, f = v2 >> 3, s = v2 & 7;
            cpa16(wb + half * 18432 + f * 144 + s * 16,
                  Wg + (size_t)f * 4096 + half * 2048 + kc * 128 + s * 16);
        }
    };

    copyW(0, 0); CPA_COMMIT();
    for (int kc = 0; kc < 16; kc++) {
        if (kc < 15) { copyW(kc + 1, (kc + 1) & 1); CPA_COMMIT(); CPA_WAIT1(); }
        else         { CPA_WAIT0(); }
        __syncthreads();   // chunk kc visible; prev compute done

        uint32_t koA = (uint32_t)kc * 128 + ks * 32;
        uint32_t a2h0[4], a2h1[4], a2l0[4], a2l1[4];
        ldsm_x4(a2h0, a2RowH + koA);
        ldsm_x4(a2h1, a2RowH + 16 * 2064 + koA);
        ldsm_x4(a2l0, a2RowL + koA);
        ldsm_x4(a2l1, a2RowL + 16 * 2064 + koA);

        uint32_t wrH = sb + WBUF + (uint32_t)(kc & 1) * 36864
                     + (fg * 32 + (lane & 15)) * 144 + ((lane >> 4) & 1) * 16
                     + ks * 32;
        uint32_t wrL = wrH + 18432;
#pragma unroll
        for (int g = 0; g < 2; g++) {
            uint32_t whq[4], wlq[4];
            ldsm_x4(whq, wrH + g * 16 * 144);
            ldsm_x4(wlq, wrL + g * 16 * 144);
#pragma unroll
            for (int s2 = 0; s2 < 2; s2++) {
                int nt = g * 2 + s2;
                mma2(D2[0][nt], a2h0, whq[s2], whq[s2 + 2]);
                mma2(D2[1][nt], a2h1, whq[s2], whq[s2 + 2]);
                mma2(D2[0][nt], a2l0, whq[s2], whq[s2 + 2]);
                mma2(D2[1][nt], a2l1, whq[s2], whq[s2 + 2]);
                mma2(D2[0][nt], a2h0, wlq[s2], wlq[s2 + 2]);
                mma2(D2[1][nt], a2h1, wlq[s2], wlq[s2 + 2]);
            }
        }
        __syncthreads();   // all warps done with buf[kc&1] before overwrite
    }

    // ---- K-reduction (4-way) via smem, then epilogue ----
    // rbuf layout: [w][p*36 + f_local], w stride 1160 floats (bank-staggered)
    float* rbuf = (float*)smem;
#pragma unroll
    for (int pm = 0; pm < 2; pm++)
#pragma unroll
        for (int nt = 0; nt < 4; nt++)
#pragma unroll
            for (int rr = 0; rr < 2; rr++) {
                int p  = pm * 16 + (lane >> 2) + rr * 8;
                int fl = nt * 8 + (lane & 3) * 2;
                float2 v;
                v.x = D2[pm][nt][rr * 2 + 0];
                v.y = D2[pm][nt][rr * 2 + 1];
                *(float2*)(rbuf + w * 1160 + p * 36 + fl) = v;
            }
    __syncthreads();

    {
        int p = t >> 4, fb = (t & 15) * 8;
        int fgr = fb >> 5, fi = fb & 31;
        float4 s0 = make_float4(0.f, 0.f, 0.f, 0.f);
        float4 s1 = make_float4(0.f, 0.f, 0.f, 0.f);
#pragma unroll
        for (int kq = 0; kq < 4; kq++) {
            const float* bp2 = rbuf + (kq * 4 + fgr) * 1160 + p * 36 + fi;
            float4 v0 = *(const float4*)bp2;
            float4 v1 = *(const float4*)(bp2 + 4);
            s0.x += v0.x; s0.y += v0.y; s0.z += v0.z; s0.w += v0.w;
            s1.x += v1.x; s1.y += v1.y; s1.z += v1.z; s1.w += v1.w;
        }
        int gi = gi0 + (p >> 2), gj = gj0 + (p & 3);
        float inv = 1.f / (g_norm[gi * I_DIM + gj] + 0.001f);
        float4 b0 = *(const float4*)(bias + fb);
        float4 b1 = *(const float4*)(bias + fb + 4);
        float* orow = out + (size_t)(gi * I_DIM + gj) * OD + fb;
        *(float4*)(orow)     = make_float4((s0.x + b0.x) * inv, (s0.y + b0.y) * inv,
                                           (s0.z + b0.z) * inv, (s0.w + b0.w) * inv);
        *(float4*)(orow + 4) = make_float4((s1.x + b1.x) * inv, (s1.y + b1.y) * inv,
                                           (s1.z + b1.z) * inv, (s1.w + b1.w) * inv);
    }
}

// ---------------------------------------------------------------------------
extern "C" void kernel_launch(void* const* d_in, const int* in_sizes, int n_in,
                              void* d_out, int out_size)
{
    const float* node = (const float*)d_in[0];
    const float* mask = (const float*)d_in[1];
    const float* Wp   = (const float*)d_in[2];
    const float* bp   = (const float*)d_in[3];
    const float* W2   = (const float*)d_in[4];
    const float* bias = (const float*)d_in[5];
    float* out = (float*)d_out;

    cudaFuncSetAttribute(ln_proj_kernel, cudaFuncAttributeMaxDynamicSharedMemorySize, 74752);
    cudaFuncSetAttribute(pair_kernel,    cudaFuncAttributeMaxDynamicSharedMemorySize, SMEM_SZ);

    ln_proj_kernel<<<6144, 256, 74752>>>(node, mask, Wp, bp);
    norm_kernel<<<576, 256>>>(mask);
    wprep_kernel<<<512, 256>>>(W2);
    pair_kernel<<<dim3(96, 48), 512, SMEM_SZ>>>(bias, out);
}